// round 8
// baseline (speedup 1.0000x reference)
#include <cuda_runtime.h>
#include <cstdint>

// Inputs (metadata order):
//  0: link_pos_seq   [1024,32,8,3]    f32
//  1: link_rot_seq   [1024,32,8,3,3]  f32
//  2: sphere_centers [8,8,3]          f32
//  3: sphere_radii   [8,8]            f32
//  4: sdf_grid       [256,256,256]    f32
//  5: weight         scalar           f32
// Output: [1024,32] f32

#define GRID_N 256
#define N_LINKS 8
#define N_SPH 8
#define TB 256

#define ROT_BYTES (TB * 9 * 4)   // 9216
#define POS_BYTES (TB * 3 * 4)   // 3072

__device__ __forceinline__ uint32_t s2u(const void* p) {
    return (uint32_t)__cvta_generic_to_shared(p);
}

// Faithfully-rounded t/0.01 (mul + 2 fma Newton correction).
__device__ __forceinline__ float div001(float t) {
    const float q0 = t * 100.0f;
    return fmaf(fmaf(-0.01f, q0, t), 100.0f, q0);
}

__device__ __forceinline__ int vox(float t) {
    int i = (int)floorf(div001(t + 1.28f));
    return min(max(i, 0), GRID_N - 1);
}

__global__ __launch_bounds__(TB, 8)
void voxel_collision_kernel(const float* __restrict__ pos,
                            const float* __restrict__ rot,
                            const float* __restrict__ cen,
                            const float* __restrict__ rad,
                            const float* __restrict__ sdf,
                            const float* __restrict__ wptr,
                            float* __restrict__ out) {
    __shared__ alignas(16) float s_rot[TB * 9];          // 9216 B (TMA dst)
    __shared__ alignas(16) float s_pos[TB * 3];          // 3072 B (TMA dst)
    __shared__ float s_cen[N_LINKS * N_SPH * 3];
    __shared__ float s_rad[N_LINKS * N_SPH];
    __shared__ alignas(8) unsigned long long s_mbar;

    const int tid = threadIdx.x;
    const int gbase = blockIdx.x * TB;
    const uint32_t mbar = s2u(&s_mbar);

    // small constants via plain LDG (1-2 lines total)
    if (tid < N_LINKS * N_SPH * 3) s_cen[tid] = cen[tid];
    if (tid < N_LINKS * N_SPH)     s_rad[tid] = rad[tid];

    if (tid == 0) {
        asm volatile("mbarrier.init.shared.b64 [%0], 1;" :: "r"(mbar) : "memory");
        asm volatile("fence.proxy.async.shared::cta;" ::: "memory");
    }
    __syncthreads();   // mbarrier init + s_cen/s_rad visible to all warps

    if (tid == 0) {
        // single arrival carrying the full expected byte count
        asm volatile("mbarrier.arrive.expect_tx.shared.b64 _, [%0], %1;"
                     :: "r"(mbar), "r"(ROT_BYTES + POS_BYTES) : "memory");
        // bulk DMA: this block's rot/pos slabs, no per-warp LSU wavefronts
        asm volatile(
            "cp.async.bulk.shared::cta.global.mbarrier::complete_tx::bytes [%0], [%1], %2, [%3];"
            :: "r"(s2u(s_rot)), "l"(rot + (size_t)gbase * 9), "r"(ROT_BYTES), "r"(mbar)
            : "memory");
        asm volatile(
            "cp.async.bulk.shared::cta.global.mbarrier::complete_tx::bytes [%0], [%1], %2, [%3];"
            :: "r"(s2u(s_pos)), "l"(pos + (size_t)gbase * 3), "r"(POS_BYTES), "r"(mbar)
            : "memory");
    }

    // acquire-wait, phase 0 (fresh barrier each launch)
    {
        uint32_t done;
        asm volatile(
            "{\n\t"
            ".reg .pred p;\n\t"
            "mbarrier.try_wait.parity.acquire.cta.shared::cta.b64 p, [%1], 0;\n\t"
            "selp.b32 %0, 1, 0, p;\n\t"
            "}" : "=r"(done) : "r"(mbar) : "memory");
        if (!done) {
            asm volatile(
                "{\n\t"
                ".reg .pred P1;\n\t"
                "WL_%=:\n\t"
                "mbarrier.try_wait.parity.acquire.cta.shared::cta.b64 P1, [%0], 0, 0x989680;\n\t"
                "@P1 bra.uni WD_%=;\n\t"
                "bra.uni WL_%=;\n\t"
                "WD_%=:\n\t"
                "}" :: "r"(mbar) : "memory");
        }
    }

    const int g = gbase + tid;
    const int l = g & 7;

    // stride-9 / stride-3 LDS: gcd(9,32)=gcd(3,32)=1 -> conflict-free
    const float r00 = s_rot[tid * 9 + 0], r01 = s_rot[tid * 9 + 1], r02 = s_rot[tid * 9 + 2];
    const float r10 = s_rot[tid * 9 + 3], r11 = s_rot[tid * 9 + 4], r12 = s_rot[tid * 9 + 5];
    const float r20 = s_rot[tid * 9 + 6], r21 = s_rot[tid * 9 + 7], r22 = s_rot[tid * 9 + 8];
    const float px = s_pos[tid * 3 + 0], py = s_pos[tid * 3 + 1], pz = s_pos[tid * 3 + 2];

    const float* lc = s_cen + l * (N_SPH * 3);
    const float* lr = s_rad + l * N_SPH;

    // 8 mutually independent gathers; ptxas front-batches the LDGs.
    float m = -3.402823466e+38f;
    #pragma unroll
    for (int s = 0; s < N_SPH; s++) {
        const float cx = lc[s * 3 + 0];
        const float cy = lc[s * 3 + 1];
        const float cz = lc[s * 3 + 2];
        const float x = fmaf(r00, cx, fmaf(r01, cy, fmaf(r02, cz, px)));
        const float y = fmaf(r10, cx, fmaf(r11, cy, fmaf(r12, cz, py)));
        const float z = fmaf(r20, cx, fmaf(r21, cy, fmaf(r22, cz, pz)));
        const float v = __ldg(sdf + ((vox(x) << 16) | (vox(y) << 8) | vox(z)));
        m = fmaxf(m, lr[s] - v);
    }

    // clip(m - 0.01, 0, 0.5) / 0.25
    float res = fminf(fmaxf(m - 0.01f, 0.0f), 0.5f) * 4.0f;

    // sum over the 8 links (adjacent lanes within the warp)
    res += __shfl_xor_sync(0xffffffffu, res, 1);
    res += __shfl_xor_sync(0xffffffffu, res, 2);
    res += __shfl_xor_sync(0xffffffffu, res, 4);

    if (l == 0) out[g >> 3] = __ldg(wptr) * res;
}

extern "C" void kernel_launch(void* const* d_in, const int* in_sizes, int n_in,
                              void* d_out, int out_size) {
    const float* pos = (const float*)d_in[0];
    const float* rot = (const float*)d_in[1];
    const float* cen = (const float*)d_in[2];
    const float* rad = (const float*)d_in[3];
    const float* sdf = (const float*)d_in[4];
    const float* w   = (const float*)d_in[5];
    float* out = (float*)d_out;

    voxel_collision_kernel<<<1024, TB>>>(pos, rot, cen, rad, sdf, w, out);
}

// round 9
// speedup vs baseline: 1.1210x; 1.1210x over previous
#include <cuda_runtime.h>

// Inputs (metadata order):
//  0: link_pos_seq   [1024,32,8,3]    f32
//  1: link_rot_seq   [1024,32,8,3,3]  f32
//  2: sphere_centers [8,8,3]          f32
//  3: sphere_radii   [8,8]            f32
//  4: sdf_grid       [256,256,256]    f32
//  5: weight         scalar           f32
// Output: [1024,32] f32

#define GRID_N 256
#define N_LINKS 8
#define N_SPH 8
#define TB 256

// Faithfully-rounded t/0.01 (mul + 2 fma Newton correction).
__device__ __forceinline__ float div001(float t) {
    const float q0 = t * 100.0f;
    return fmaf(fmaf(-0.01f, q0, t), 100.0f, q0);
}

__device__ __forceinline__ int vox(float t) {
    int i = (int)floorf(div001(t + 1.28f));
    return min(max(i, 0), GRID_N - 1);
}

__global__ __launch_bounds__(TB, 8)
void voxel_collision_kernel(const float* __restrict__ pos,
                            const float* __restrict__ rot,
                            const float* __restrict__ cen,
                            const float* __restrict__ rad,
                            const float* __restrict__ sdf,
                            const float* __restrict__ wptr,
                            float* __restrict__ out) {
    __shared__ float s_cen[N_LINKS * N_SPH * 3];   // 768 B
    __shared__ float s_rad[N_LINKS * N_SPH];       // 256 B

    const int tid = threadIdx.x;
    if (tid < N_LINKS * N_SPH * 3) s_cen[tid] = cen[tid];
    if (tid < N_LINKS * N_SPH)     s_rad[tid] = rad[tid];
    __syncthreads();

    // thread = (bh, link, sphere-half): 524288 threads total
    const int t = blockIdx.x * TB + tid;
    const int g = t >> 1;        // (bh, link) item, 0..262143
    const int l = g & 7;         // link id
    const int h = t & 1;         // sphere half: spheres 4h .. 4h+3

    const float* R = rot + (size_t)g * 9;
    const float r00 = __ldg(R + 0), r01 = __ldg(R + 1), r02 = __ldg(R + 2);
    const float r10 = __ldg(R + 3), r11 = __ldg(R + 4), r12 = __ldg(R + 5);
    const float r20 = __ldg(R + 6), r21 = __ldg(R + 7), r22 = __ldg(R + 8);
    const float* P = pos + (size_t)g * 3;
    const float px = __ldg(P + 0), py = __ldg(P + 1), pz = __ldg(P + 2);

    const float* lc = s_cen + l * (N_SPH * 3) + h * 12;  // this half's 4 centers
    const float* lr = s_rad + l * N_SPH + h * 4;

    // 4 mutually independent gathers per thread
    float m = -3.402823466e+38f;
    #pragma unroll
    for (int k = 0; k < 4; k++) {
        const float cx = lc[k * 3 + 0];
        const float cy = lc[k * 3 + 1];
        const float cz = lc[k * 3 + 2];
        const float x = fmaf(r00, cx, fmaf(r01, cy, fmaf(r02, cz, px)));
        const float y = fmaf(r10, cx, fmaf(r11, cy, fmaf(r12, cz, py)));
        const float z = fmaf(r20, cx, fmaf(r21, cy, fmaf(r22, cz, pz)));
        const float v = __ldg(sdf + ((vox(x) << 16) | (vox(y) << 8) | vox(z)));
        m = fmaxf(m, lr[k] - v);
    }

    // combine the two sphere halves (lane bit 0)
    m = fmaxf(m, __shfl_xor_sync(0xffffffffu, m, 1));

    // per-link cost
    float res = fminf(fmaxf(m - 0.01f, 0.0f), 0.5f) * 4.0f;

    // sum over the 8 links (lane bits 1..3)
    res += __shfl_xor_sync(0xffffffffu, res, 2);
    res += __shfl_xor_sync(0xffffffffu, res, 4);
    res += __shfl_xor_sync(0xffffffffu, res, 8);

    if ((t & 15) == 0) out[t >> 4] = __ldg(wptr) * res;
}

extern "C" void kernel_launch(void* const* d_in, const int* in_sizes, int n_in,
                              void* d_out, int out_size) {
    const float* pos = (const float*)d_in[0];
    const float* rot = (const float*)d_in[1];
    const float* cen = (const float*)d_in[2];
    const float* rad = (const float*)d_in[3];
    const float* sdf = (const float*)d_in[4];
    const float* w   = (const float*)d_in[5];
    float* out = (float*)d_out;

    // 524288 threads (half-item each), 256 per block -> 2048 blocks (~1.7 waves)
    voxel_collision_kernel<<<2048, TB>>>(pos, rot, cen, rad, sdf, w, out);
}